// round 17
// baseline (speedup 1.0000x reference)
#include <cuda_runtime.h>
#include <cuda_bf16.h>
#include <cstdint>
#include <string.h>
#include <math.h>

#define BSZ 4096
#define DIM 256
#define NF  12288            // 3 * BSZ rows: [A ; P0 ; P1]
#define MARGIN 1.0f
#define EPSQ 1e-12f
#define QS   254.0f          // int8 quantization scale
#define RSTRIDE 80           // smem row stride in bytes (64B data + 16B pad)
#define OPBYTES   (128 * RSTRIDE)         // one operand, one stage: 10240 B
#define STAGEBYTES (2 * OPBYTES)          // A + B per stage: 20480 B
#define NSTAGE 3
#define SMEM_DYN (NSTAGE * STAGEBYTES + 512)

typedef unsigned long long ull;

// ---------------- scratch (__device__ globals; no allocs allowed) -----------
__device__ signed char g_Fi[NF * DIM];   // normalized rows, int8 (GEMM)
__device__ float       g_F [NF * DIM];   // normalized rows, fp32 (rescore)
__device__ float       g_pos[2 * BSZ];   // exact fp32 dot(a_i, p_{i,v})
__device__ ull         g_key64[3 * BSZ]; // (ordered-s32 << 32) | argmax index
__device__ float       g_loss[2 * BSZ];

__device__ __forceinline__ uint32_t smem_to_u32(const void* p) {
    uint32_t a;
    asm("{ .reg .u64 t; cvta.to.shared.u64 t, %1; cvt.u32.u64 %0, t; }" : "=r"(a) : "l"(p));
    return a;
}
__device__ __forceinline__ void cp_async16(uint32_t saddr, const void* gaddr) {
    asm volatile("cp.async.ca.shared.global [%0], [%1], 16;"
                 :: "r"(saddr), "l"(gaddr) : "memory");
}
#define CP_COMMIT()  asm volatile("cp.async.commit_group;" ::: "memory")
#define CP_WAIT(n)   asm volatile("cp.async.wait_group %0;" :: "n"(n) : "memory")

__device__ __forceinline__ uint32_t q4pack(float x0, float x1, float x2, float x3) {
    int q0 = __float2int_rn(fminf(fmaxf(x0 * QS, -127.f), 127.f));
    int q1 = __float2int_rn(fminf(fmaxf(x1 * QS, -127.f), 127.f));
    int q2 = __float2int_rn(fminf(fmaxf(x2 * QS, -127.f), 127.f));
    int q3 = __float2int_rn(fminf(fmaxf(x3 * QS, -127.f), 127.f));
    return (q0 & 255) | ((q1 & 255) << 8) | ((q2 & 255) << 16) | ((q3 & 255) << 24);
}
__device__ __forceinline__ ull umax64(ull a, ull b) { return a > b ? a : b; }

// ============================================================================
// Kernel 1: warp-per-row normalize -> fp32 + int8 features; exact pos dots.
// ============================================================================
__global__ __launch_bounds__(256) void normalize_kernel(
    const float* __restrict__ anchor, const float* __restrict__ positive) {
    int gw   = (blockIdx.x * 256 + threadIdx.x) >> 5;   // row 0..4095
    int lane = threadIdx.x & 31;

    const float4* a4 = (const float4*)(anchor + (size_t)gw * DIM);
    float4 a0 = a4[lane * 2], a1 = a4[lane * 2 + 1];
    float ss = a0.x*a0.x + a0.y*a0.y + a0.z*a0.z + a0.w*a0.w
             + a1.x*a1.x + a1.y*a1.y + a1.z*a1.z + a1.w*a1.w;
    #pragma unroll
    for (int o = 16; o; o >>= 1) ss += __shfl_xor_sync(0xffffffffu, ss, o);
    float inv = 1.0f / fmaxf(sqrtf(ss), 1e-12f);
    a0.x *= inv; a0.y *= inv; a0.z *= inv; a0.w *= inv;
    a1.x *= inv; a1.y *= inv; a1.z *= inv; a1.w *= inv;
    ((float4*)(g_F + (size_t)gw * DIM))[lane * 2]     = a0;
    ((float4*)(g_F + (size_t)gw * DIM))[lane * 2 + 1] = a1;
    {
        uint2 o;
        o.x = q4pack(a0.x, a0.y, a0.z, a0.w);
        o.y = q4pack(a1.x, a1.y, a1.z, a1.w);
        ((uint2*)(g_Fi + (size_t)gw * DIM))[lane] = o;
    }

    #pragma unroll
    for (int v = 0; v < 2; v++) {
        const float4* p4 = (const float4*)(positive + ((size_t)gw * 2 + v) * DIM);
        float4 p0 = p4[lane * 2], p1 = p4[lane * 2 + 1];
        float ps = p0.x*p0.x + p0.y*p0.y + p0.z*p0.z + p0.w*p0.w
                 + p1.x*p1.x + p1.y*p1.y + p1.z*p1.z + p1.w*p1.w;
        #pragma unroll
        for (int o = 16; o; o >>= 1) ps += __shfl_xor_sync(0xffffffffu, ps, o);
        float pinv = 1.0f / fmaxf(sqrtf(ps), 1e-12f);
        p0.x *= pinv; p0.y *= pinv; p0.z *= pinv; p0.w *= pinv;
        p1.x *= pinv; p1.y *= pinv; p1.z *= pinv; p1.w *= pinv;
        size_t rr = (size_t)(1 + v) * BSZ + gw;
        ((float4*)(g_F + rr * DIM))[lane * 2]     = p0;
        ((float4*)(g_F + rr * DIM))[lane * 2 + 1] = p1;
        uint2 o;
        o.x = q4pack(p0.x, p0.y, p0.z, p0.w);
        o.y = q4pack(p1.x, p1.y, p1.z, p1.w);
        ((uint2*)(g_Fi + rr * DIM))[lane] = o;

        float pd = a0.x*p0.x + a0.y*p0.y + a0.z*p0.z + a0.w*p0.w
                 + a1.x*p1.x + a1.y*p1.y + a1.z*p1.z + a1.w*p1.w;
        #pragma unroll
        for (int o2 = 16; o2; o2 >>= 1) pd += __shfl_xor_sync(0xffffffffu, pd, o2);
        if (lane == 0) g_pos[v * BSZ + gw] = pd;
    }
    if (lane < 3) g_key64[lane * BSZ + gw] = 0ull;
}

// ============================================================================
// Kernel 2: int8 mma GEMM (m16n8k32.s8, exact s32 dots of quantized features)
// + fused masked row-ARGMAX via packed 64-bit atomicMax.
// CTA tile 128x128, K=256 bytes in 4 iters of 64B; 3-stage cp.async.
// mat0 symmetry: skip lower tiles; upper tiles also feed column argmax.
// ============================================================================
__global__ __launch_bounds__(256) void gemm_max_mma(const int* __restrict__ labels) {
    int rowBase = blockIdx.y * 128;    // [0, 4096)
    int colBase = blockIdx.x * 128;    // [0, 12288)
    int mat     = colBase >> 12;

    if (mat == 0 && colBase < rowBase) return;
    bool sym = (mat == 0) && (colBase > rowBase);

    extern __shared__ char dsm[];
    uint32_t sbase = smem_to_u32(dsm);
    int* clab = (int*)(dsm + NSTAGE * STAGEBYTES);

    int tid = threadIdx.x, lane = tid & 31, wid = tid >> 5;
    if (tid < 128) clab[tid] = labels[(colBase & (BSZ - 1)) + tid];

    int warpM = wid & 3;               // 4 warps along M (32 rows each)
    int warpN = wid >> 2;              // 2 warps along N (64 cols each)

    // ldmatrix lane offsets (bytes, within one operand); +32 B per ks (k=32)
    // tiles: lanes0-7 rows0-7@b0, 8-15 rows8-15@b0, 16-23 rows0-7@b16, 24-31 rows8-15@b16
    uint32_t offA[2], offB[4];
    #pragma unroll
    for (int mt = 0; mt < 2; mt++) {
        int r  = warpM * 32 + mt * 16 + (lane & 15);
        int kc = (lane >> 4) * 16;
        offA[mt] = (uint32_t)(r * RSTRIDE + kc);
    }
    #pragma unroll
    for (int np = 0; np < 4; np++) {
        int n  = warpN * 64 + np * 16 + (lane & 15);
        int kc = (lane >> 4) * 16;
        offB[np] = (uint32_t)(n * RSTRIDE + kc);
    }

    int acc[2][8][4];
    #pragma unroll
    for (int mt = 0; mt < 2; mt++)
        #pragma unroll
        for (int nt = 0; nt < 8; nt++)
            #pragma unroll
            for (int c = 0; c < 4; c++) acc[mt][nt][c] = 0;

    // Loader: 256 threads cover 64 rows x 64 B per pass (A:2 passes, B:2).
    int ldrow = tid >> 2, ldg = (tid & 3) * 16;    // 16 B per cp
    const signed char* gA = g_Fi + (size_t)(rowBase + ldrow) * DIM + ldg;
    const signed char* gB = g_Fi + (size_t)(colBase + ldrow) * DIM + ldg;
    uint32_t srow = (uint32_t)(ldrow * RSTRIDE + ldg);

    auto issue = [&](int stg, int kt) {
        uint32_t so = sbase + (uint32_t)stg * STAGEBYTES;
        #pragma unroll
        for (int p = 0; p < 2; p++) {
            uint32_t ro = (uint32_t)(p * 64 * RSTRIDE) + srow;
            cp_async16(so + ro,           gA + (size_t)p * 64 * DIM + kt);
            cp_async16(so + OPBYTES + ro, gB + (size_t)p * 64 * DIM + kt);
        }
    };

    issue(0, 0);  CP_COMMIT();
    issue(1, 64); CP_COMMIT();

    #pragma unroll
    for (int i = 0; i < 4; i++) {
        if (i < 3) { CP_WAIT(1); } else { CP_WAIT(0); }
        __syncthreads();                       // stage i ready; stage (i+2)%3 free
        if (i < 2) { issue((i + 2) % NSTAGE, (i + 2) * 64); CP_COMMIT(); }

        uint32_t sa = sbase + (uint32_t)(i % NSTAGE) * STAGEBYTES;
        uint32_t sb = sa + OPBYTES;
        #pragma unroll
        for (int ks = 0; ks < 2; ks++) {
            uint32_t a[2][4], b[4][4];
            #pragma unroll
            for (int mt = 0; mt < 2; mt++)
                asm volatile("ldmatrix.sync.aligned.m8n8.x4.shared.b16 "
                             "{%0,%1,%2,%3}, [%4];"
                             : "=r"(a[mt][0]), "=r"(a[mt][1]),
                               "=r"(a[mt][2]), "=r"(a[mt][3])
                             : "r"(sa + offA[mt] + ks * 32u));
            #pragma unroll
            for (int np = 0; np < 4; np++)
                asm volatile("ldmatrix.sync.aligned.m8n8.x4.shared.b16 "
                             "{%0,%1,%2,%3}, [%4];"
                             : "=r"(b[np][0]), "=r"(b[np][1]),
                               "=r"(b[np][2]), "=r"(b[np][3])
                             : "r"(sb + offB[np] + ks * 32u));
            #pragma unroll
            for (int mt = 0; mt < 2; mt++)
                #pragma unroll
                for (int nt = 0; nt < 8; nt++) {
                    int np = nt >> 1, sub = nt & 1;
                    uint32_t b0 = b[np][sub];       // k 0-15 of this ks
                    uint32_t b1 = b[np][sub + 2];   // k 16-31
                    asm volatile(
                        "mma.sync.aligned.m16n8k32.row.col.s32.s8.s8.s32 "
                        "{%0,%1,%2,%3}, {%4,%5,%6,%7}, {%8,%9}, {%0,%1,%2,%3};"
                        : "+r"(acc[mt][nt][0]), "+r"(acc[mt][nt][1]),
                          "+r"(acc[mt][nt][2]), "+r"(acc[mt][nt][3])
                        : "r"(a[mt][0]), "r"(a[mt][1]), "r"(a[mt][2]), "r"(a[mt][3]),
                          "r"(b0), "r"(b1));
                }
        }
    }

    // ---- Epilogue pass 1: masked row-argmax, packed (value,index) keys ----
    int gid = lane >> 2, qid = lane & 3;
    int colInMat = colBase & (BSZ - 1);
    #pragma unroll
    for (int mt = 0; mt < 2; mt++)
        #pragma unroll
        for (int half = 0; half < 2; half++) {
            int grow = rowBase + warpM * 32 + mt * 16 + half * 8 + gid;
            int rl   = labels[grow];
            ull best = 0ull;
            #pragma unroll
            for (int nt = 0; nt < 8; nt++) {
                int c0 = warpN * 64 + nt * 8 + qid * 2;
                unsigned u0 = (clab[c0]     != rl)
                            ? ((unsigned)acc[mt][nt][half * 2]     ^ 0x80000000u) : 0u;
                unsigned u1 = (clab[c0 + 1] != rl)
                            ? ((unsigned)acc[mt][nt][half * 2 + 1] ^ 0x80000000u) : 0u;
                acc[mt][nt][half * 2]     = (int)u0;   // keep masked for pass 2
                acc[mt][nt][half * 2 + 1] = (int)u1;
                best = umax64(best, ((ull)u0 << 32) | (unsigned)(colInMat + c0));
                best = umax64(best, ((ull)u1 << 32) | (unsigned)(colInMat + c0 + 1));
            }
            best = umax64(best, __shfl_xor_sync(0xffffffffu, best, 1));
            best = umax64(best, __shfl_xor_sync(0xffffffffu, best, 2));
            if (qid == 0)
                atomicMax(&g_key64[mat * BSZ + grow], best);
        }

    // ---- Pass 2 (symmetric off-diag mat0): column-argmax -> row colBase+c ----
    if (sym) {
        #pragma unroll
        for (int nt = 0; nt < 8; nt++)
            #pragma unroll
            for (int j = 0; j < 2; j++) {
                ull best = 0ull;
                #pragma unroll
                for (int mt = 0; mt < 2; mt++)
                    #pragma unroll
                    for (int half = 0; half < 2; half++) {
                        unsigned u = (unsigned)acc[mt][nt][half * 2 + j];
                        unsigned r = (unsigned)(rowBase + warpM * 32 + mt * 16
                                                + half * 8 + gid);
                        best = umax64(best, ((ull)u << 32) | r);
                    }
                #pragma unroll
                for (int o = 4; o <= 16; o <<= 1)
                    best = umax64(best, __shfl_xor_sync(0xffffffffu, best, o));
                if (gid == 0) {
                    int col = colBase + warpN * 64 + nt * 8 + qid * 2 + j;
                    atomicMax(&g_key64[col], best);
                }
            }
    }
}

// ============================================================================
// Kernel 3: exact fp32 rescore of the 3 argmax candidates. 1 warp per row.
// ============================================================================
__global__ __launch_bounds__(256) void rescore_kernel() {
    int gw   = (blockIdx.x * 256 + threadIdx.x) >> 5;   // row 0..4095
    int lane = threadIdx.x & 31;

    const float4* a4 = (const float4*)(g_F + (size_t)gw * DIM);
    float4 av0 = a4[lane * 2], av1 = a4[lane * 2 + 1];

    float dots[3];
    #pragma unroll
    for (int m = 0; m < 3; m++) {
        unsigned idx = (unsigned)(g_key64[m * BSZ + gw] & 0xffffffffu);
        const float4* f4 = (const float4*)(g_F + ((size_t)m * BSZ + idx) * DIM);
        float4 b0 = f4[lane * 2], b1 = f4[lane * 2 + 1];
        float s = av0.x*b0.x + av0.y*b0.y + av0.z*b0.z + av0.w*b0.w
                + av1.x*b1.x + av1.y*b1.y + av1.z*b1.z + av1.w*b1.w;
        #pragma unroll
        for (int o = 16; o; o >>= 1) s += __shfl_xor_sync(0xffffffffu, s, o);
        dots[m] = s;
    }

    if (lane == 0) {
        #pragma unroll
        for (int v = 0; v < 2; v++) {
            float best = fmaxf(dots[0], dots[1 + v]);
            float neg  = sqrtf(fmaxf(2.0f - 2.0f * best, EPSQ));
            float pos  = sqrtf(fmaxf(2.0f - 2.0f * g_pos[v * BSZ + gw], EPSQ));
            g_loss[v * BSZ + gw] = fmaxf(pos - neg + MARGIN, 0.0f);
        }
    }
}

// ============================================================================
// Kernel 4: deterministic fixed-order reduction -> scalar mean
// ============================================================================
__global__ __launch_bounds__(1024) void reduce_kernel(float* __restrict__ out) {
    __shared__ float sm[32];
    float sum = 0.0f;
    for (int i = threadIdx.x; i < 2 * BSZ; i += 1024) sum += g_loss[i];
    #pragma unroll
    for (int o = 16; o; o >>= 1) sum += __shfl_down_sync(0xffffffffu, sum, o);
    int w = threadIdx.x >> 5, l = threadIdx.x & 31;
    if (l == 0) sm[w] = sum;
    __syncthreads();
    if (w == 0) {
        float t = sm[l];
        #pragma unroll
        for (int o = 16; o; o >>= 1) t += __shfl_down_sync(0xffffffffu, t, o);
        if (l == 0) out[0] = t / (2.0f * BSZ);
    }
}

// ============================================================================
extern "C" void kernel_launch(void* const* d_in, const int* in_sizes, int n_in,
                              void* d_out, int out_size) {
    const float* anchor   = (const float*)d_in[0];
    const float* positive = (const float*)d_in[1];
    const int*   labels   = (const int*)d_in[2];
    float*       out      = (float*)d_out;

    cudaFuncSetAttribute(gemm_max_mma,
                         cudaFuncAttributeMaxDynamicSharedMemorySize, SMEM_DYN);

    normalize_kernel<<<BSZ / 8, 256>>>(anchor, positive);
    gemm_max_mma<<<dim3(NF / 128, BSZ / 128), 256, SMEM_DYN>>>(labels);
    rescore_kernel<<<BSZ / 8, 256>>>();
    reduce_kernel<<<1, 1024>>>(out);
}